// round 13
// baseline (speedup 1.0000x reference)
#include <cuda_runtime.h>
#include <cstdint>

#define B_TOT 32768
#define F_TOT 256
#define H1 16
#define H2 8

#define BB 256   // batch elements per block
#define FT 8     // features per block (one warp per feature)
#define NP 4     // f32x2 pairs per thread (8 batch elements)

typedef unsigned long long u64;

__device__ __forceinline__ u64 f2pack(float lo, float hi) {
    u64 r; asm("mov.b64 %0, {%1, %2};" : "=l"(r) : "f"(lo), "f"(hi)); return r;
}
__device__ __forceinline__ void f2unpack(u64 p, float& lo, float& hi) {
    asm("mov.b64 {%0, %1}, %2;" : "=f"(lo), "=f"(hi) : "l"(p));
}
__device__ __forceinline__ u64 fma2(u64 a, u64 b, u64 c) {
    u64 r; asm("fma.rn.f32x2 %0, %1, %2, %3;" : "=l"(r) : "l"(a), "l"(b), "l"(c)); return r;
}
__device__ __forceinline__ float ex2f(float x) {
    float r; asm("ex2.approx.ftz.f32 %0, %1;" : "=f"(r) : "f"(x)); return r;
}

// Packed ELU, proven R3/R5/R7 version — do not modify:
// unpack + 2x FMUL-imm + 2x MUFU + 2x FADD + 2x FSETP/FSEL + pack
__device__ __forceinline__ u64 elu2(u64 v2) {
    float v0, v1; f2unpack(v2, v0, v1);
    float e0 = ex2f(v0 * 1.4426950408889634f);
    float e1 = ex2f(v1 * 1.4426950408889634f);
    float r0 = v0 > 0.0f ? v0 : e0 - 1.0f;
    float r1 = v1 > 0.0f ? v1 : e1 - 1.0f;
    return f2pack(r0, r1);
}

__global__ __launch_bounds__(256) void mlp_z_kernel(
    const float* __restrict__ x,
    const float* __restrict__ W1, const float* __restrict__ b1,
    const float* __restrict__ W2, const float* __restrict__ b2,
    const float* __restrict__ W3, const float* __restrict__ b3,
    const float* __restrict__ theta,
    const float* __restrict__ bias,
    float* __restrict__ Z,
    float* __restrict__ y)
{
    __shared__ float s_x[FT][BB];     // 8 KB
    __shared__ float s_z[FT][BB];     // 8 KB
    // Duplicated {w, w} pairs: packed operand in one broadcast LDS.64
    __shared__ u64 sW1d[FT * H1];
    __shared__ u64 sb1d[FT * H1];
    __shared__ u64 sW2d[FT * H1 * H2];
    __shared__ u64 sb2d[FT * H2];
    __shared__ u64 sW3d[FT * H2];
    __shared__ float sb3[FT];
    __shared__ float s_sw[FT];        // softplus(theta) for this feature group

    const int t  = threadIdx.x;
    const int b0 = blockIdx.x * BB;
    const int f0 = blockIdx.y * FT;

    // ---- params -> smem (duplicated into f32x2) ----
    if (t < FT * H1) {
        float w = W1[f0 * H1 + t];  sW1d[t] = f2pack(w, w);
        float b = b1[f0 * H1 + t];  sb1d[t] = f2pack(b, b);
    }
    #pragma unroll
    for (int i = t; i < FT * H1 * H2; i += 256) {
        float w = W2[f0 * H1 * H2 + i];  sW2d[i] = f2pack(w, w);
    }
    if (t < FT * H2) {
        float b = b2[f0 * H2 + t];  sb2d[t] = f2pack(b, b);
        float w = W3[f0 * H2 + t];  sW3d[t] = f2pack(w, w);
    }
    if (t < FT) {
        sb3[t] = b3[f0 + t];
        s_sw[t] = log1pf(__expf(theta[f0 + t]));
    }

    // ---- x tile [BB x FT] coalesced float4 -> f-major smem ----
    #pragma unroll
    for (int i = t; i < BB * 2; i += 256) {
        const int bl = i >> 1;
        const int fq = (i & 1) * 4;
        const float4 v = *reinterpret_cast<const float4*>(
            x + (size_t)(b0 + bl) * F_TOT + f0 + fq);
        s_x[fq + 0][bl] = v.x;
        s_x[fq + 1][bl] = v.y;
        s_x[fq + 2][bl] = v.z;
        s_x[fq + 3][bl] = v.w;
    }
    __syncthreads();

    const int w = t >> 5;
    const int l = t & 31;

    u64 xp[NP];
    #pragma unroll
    for (int u = 0; u < NP; u++)
        xp[u] = f2pack(s_x[w][l + 64 * u], s_x[w][l + 64 * u + 32]);

    u64 acc[NP][H2];
    #pragma unroll
    for (int k = 0; k < H2; k++) {
        const u64 bv = sb2d[w * H2 + k];
        #pragma unroll
        for (int u = 0; u < NP; u++) acc[u][k] = bv;
    }

    #pragma unroll
    for (int h = 0; h < H1; h++) {
        const u64 w1 = sW1d[w * H1 + h];
        const u64 bb = sb1d[w * H1 + h];
        u64 h1p[NP];
        #pragma unroll
        for (int u = 0; u < NP; u++)
            h1p[u] = elu2(fma2(xp[u], w1, bb));
        #pragma unroll
        for (int k = 0; k < H2; k++) {
            const u64 w2 = sW2d[(w * H1 + h) * H2 + k];
            #pragma unroll
            for (int u = 0; u < NP; u++)
                acc[u][k] = fma2(h1p[u], w2, acc[u][k]);
        }
    }

    // epilogue: Z = elu(acc) . W3 + b3
    {
        const float b3v = sb3[w];
        #pragma unroll
        for (int u = 0; u < NP; u++) {
            u64 z = f2pack(b3v, b3v);
            #pragma unroll
            for (int k = 0; k < H2; k++)
                z = fma2(elu2(acc[u][k]), sW3d[w * H2 + k], z);
            float z0, z1; f2unpack(z, z0, z1);
            s_z[w][l + 64 * u]      = z0;
            s_z[w][l + 64 * u + 32] = z1;
        }
    }
    __syncthreads();

    // ---- Z tile -> gmem coalesced float4 ----
    #pragma unroll
    for (int i = t; i < BB * 2; i += 256) {
        const int bl = i >> 1;
        const int fq = (i & 1) * 4;
        float4 v;
        v.x = s_z[fq + 0][bl];
        v.y = s_z[fq + 1][bl];
        v.z = s_z[fq + 2][bl];
        v.w = s_z[fq + 3][bl];
        *reinterpret_cast<float4*>(Z + (size_t)(b0 + bl) * F_TOT + f0 + fq) = v;
    }

    // ---- fused reduction straight into y via REDG (y pre-zeroed by memset) ----
    {
        float ps = 0.0f;
        #pragma unroll
        for (int f = 0; f < FT; f++)
            ps = fmaf(s_z[f][t], s_sw[f], ps);
        if (blockIdx.y == 0) ps += bias[0];   // bias added exactly once per b
        atomicAdd(&y[b0 + t], ps);            // no return use -> REDG
    }
}

// weights = softplus(theta); single tiny block.
__global__ __launch_bounds__(256) void weights_kernel(
    const float* __restrict__ theta, float* __restrict__ wout)
{
    const int t = threadIdx.x;
    wout[t] = log1pf(__expf(theta[t]));
}

extern "C" void kernel_launch(void* const* d_in, const int* in_sizes, int n_in,
                              void* d_out, int out_size)
{
    const float* x     = (const float*)d_in[0];
    const float* W1    = (const float*)d_in[1];
    const float* b1    = (const float*)d_in[2];
    const float* W2    = (const float*)d_in[3];
    const float* b2    = (const float*)d_in[4];
    const float* W3    = (const float*)d_in[5];
    const float* b3    = (const float*)d_in[6];
    const float* theta = (const float*)d_in[7];
    const float* bias  = (const float*)d_in[8];

    float* out = (float*)d_out;
    float* y    = out;                 // [B]
    float* wout = out + B_TOT;         // [F]
    float* Z    = out + B_TOT + F_TOT; // [B, F]

    // zero y (accumulated by REDG atomics in mlp_z_kernel)
    cudaMemsetAsync(y, 0, B_TOT * sizeof(float));

    weights_kernel<<<1, F_TOT>>>(theta, wout);

    dim3 grid(B_TOT / BB, F_TOT / FT);   // (128, 32)
    mlp_z_kernel<<<grid, 256>>>(x, W1, b1, W2, b2, W3, b3, theta, bias, Z, y);
}

// round 14
// speedup vs baseline: 1.4755x; 1.4755x over previous
#include <cuda_runtime.h>
#include <cstdint>

#define B_TOT 32768
#define F_TOT 256
#define H1 16
#define H2 8

#define BB 256   // batch elements per block
#define FT 8     // features per block (one warp per feature)
#define NP 4     // f32x2 pairs per thread (8 batch elements)
#define NFG (F_TOT / FT)   // 32 feature groups
#define NCOL (B_TOT / BB)  // 128 batch columns

typedef unsigned long long u64;

// scratch: per-(feature-group, batch) partial dot products  (4 MB)
__device__ float g_partial[NFG * B_TOT];
// arrival counters, one per batch column (zero-initialized; reset each run)
__device__ int g_cnt[NCOL];

__device__ __forceinline__ u64 f2pack(float lo, float hi) {
    u64 r; asm("mov.b64 %0, {%1, %2};" : "=l"(r) : "f"(lo), "f"(hi)); return r;
}
__device__ __forceinline__ void f2unpack(u64 p, float& lo, float& hi) {
    asm("mov.b64 {%0, %1}, %2;" : "=f"(lo), "=f"(hi) : "l"(p));
}
__device__ __forceinline__ u64 fma2(u64 a, u64 b, u64 c) {
    u64 r; asm("fma.rn.f32x2 %0, %1, %2, %3;" : "=l"(r) : "l"(a), "l"(b), "l"(c)); return r;
}
__device__ __forceinline__ float ex2f(float x) {
    float r; asm("ex2.approx.ftz.f32 %0, %1;" : "=f"(r) : "f"(x)); return r;
}

// Packed ELU, proven R3/R5/R7 version — do not modify:
__device__ __forceinline__ u64 elu2(u64 v2) {
    float v0, v1; f2unpack(v2, v0, v1);
    float e0 = ex2f(v0 * 1.4426950408889634f);
    float e1 = ex2f(v1 * 1.4426950408889634f);
    float r0 = v0 > 0.0f ? v0 : e0 - 1.0f;
    float r1 = v1 > 0.0f ? v1 : e1 - 1.0f;
    return f2pack(r0, r1);
}

__global__ __launch_bounds__(256) void mlp_z_kernel(
    const float* __restrict__ x,
    const float* __restrict__ W1, const float* __restrict__ b1,
    const float* __restrict__ W2, const float* __restrict__ b2,
    const float* __restrict__ W3, const float* __restrict__ b3,
    const float* __restrict__ theta,
    const float* __restrict__ bias,
    float* __restrict__ Z,
    float* __restrict__ y)
{
    __shared__ float s_x[FT][BB];     // 8 KB
    __shared__ float s_z[FT][BB];     // 8 KB
    // Duplicated {w, w} pairs: packed operand in one broadcast LDS.64
    __shared__ u64 sW1d[FT * H1];
    __shared__ u64 sb1d[FT * H1];
    __shared__ u64 sW2d[FT * H1 * H2];
    __shared__ u64 sb2d[FT * H2];
    __shared__ u64 sW3d[FT * H2];
    __shared__ float sb3[FT];
    __shared__ float s_sw[FT];        // softplus(theta) for this feature group
    __shared__ int s_last;            // is this the last block for this column?

    const int t  = threadIdx.x;
    const int b0 = blockIdx.x * BB;
    const int f0 = blockIdx.y * FT;

    // ---- params -> smem (duplicated into f32x2) ----
    if (t < FT * H1) {
        float w = W1[f0 * H1 + t];  sW1d[t] = f2pack(w, w);
        float b = b1[f0 * H1 + t];  sb1d[t] = f2pack(b, b);
    }
    #pragma unroll
    for (int i = t; i < FT * H1 * H2; i += 256) {
        float w = W2[f0 * H1 * H2 + i];  sW2d[i] = f2pack(w, w);
    }
    if (t < FT * H2) {
        float b = b2[f0 * H2 + t];  sb2d[t] = f2pack(b, b);
        float w = W3[f0 * H2 + t];  sW3d[t] = f2pack(w, w);
    }
    if (t < FT) {
        sb3[t] = b3[f0 + t];
        s_sw[t] = log1pf(__expf(theta[f0 + t]));
    }

    // ---- x tile [BB x FT] coalesced float4 -> f-major smem ----
    #pragma unroll
    for (int i = t; i < BB * 2; i += 256) {
        const int bl = i >> 1;
        const int fq = (i & 1) * 4;
        const float4 v = *reinterpret_cast<const float4*>(
            x + (size_t)(b0 + bl) * F_TOT + f0 + fq);
        s_x[fq + 0][bl] = v.x;
        s_x[fq + 1][bl] = v.y;
        s_x[fq + 2][bl] = v.z;
        s_x[fq + 3][bl] = v.w;
    }
    __syncthreads();

    const int w = t >> 5;
    const int l = t & 31;

    u64 xp[NP];
    #pragma unroll
    for (int u = 0; u < NP; u++)
        xp[u] = f2pack(s_x[w][l + 64 * u], s_x[w][l + 64 * u + 32]);

    u64 acc[NP][H2];
    #pragma unroll
    for (int k = 0; k < H2; k++) {
        const u64 bv = sb2d[w * H2 + k];
        #pragma unroll
        for (int u = 0; u < NP; u++) acc[u][k] = bv;
    }

    #pragma unroll
    for (int h = 0; h < H1; h++) {
        const u64 w1 = sW1d[w * H1 + h];
        const u64 bb = sb1d[w * H1 + h];
        u64 h1p[NP];
        #pragma unroll
        for (int u = 0; u < NP; u++)
            h1p[u] = elu2(fma2(xp[u], w1, bb));
        #pragma unroll
        for (int k = 0; k < H2; k++) {
            const u64 w2 = sW2d[(w * H1 + h) * H2 + k];
            #pragma unroll
            for (int u = 0; u < NP; u++)
                acc[u][k] = fma2(h1p[u], w2, acc[u][k]);
        }
    }

    // epilogue: Z = elu(acc) . W3 + b3
    {
        const float b3v = sb3[w];
        #pragma unroll
        for (int u = 0; u < NP; u++) {
            u64 z = f2pack(b3v, b3v);
            #pragma unroll
            for (int k = 0; k < H2; k++)
                z = fma2(elu2(acc[u][k]), sW3d[w * H2 + k], z);
            float z0, z1; f2unpack(z, z0, z1);
            s_z[w][l + 64 * u]      = z0;
            s_z[w][l + 64 * u + 32] = z1;
        }
    }
    __syncthreads();

    // ---- Z tile -> gmem coalesced float4 ----
    #pragma unroll
    for (int i = t; i < BB * 2; i += 256) {
        const int bl = i >> 1;
        const int fq = (i & 1) * 4;
        float4 v;
        v.x = s_z[fq + 0][bl];
        v.y = s_z[fq + 1][bl];
        v.z = s_z[fq + 2][bl];
        v.w = s_z[fq + 3][bl];
        *reinterpret_cast<float4*>(Z + (size_t)(b0 + bl) * F_TOT + f0 + fq) = v;
    }

    // ---- fused partial reduction (plain coalesced STG, no data atomics) ----
    {
        float ps = 0.0f;
        #pragma unroll
        for (int f = 0; f < FT; f++)
            ps = fmaf(s_z[f][t], s_sw[f], ps);
        g_partial[blockIdx.y * B_TOT + b0 + t] = ps;
    }

    // ---- last-block-per-column does the final y reduction ----
    __threadfence();                       // make this block's partial visible
    __syncthreads();
    if (t == 0) {
        int old = atomicAdd(&g_cnt[blockIdx.x], 1);
        s_last = (old == NFG - 1);
        if (s_last) g_cnt[blockIdx.x] = 0; // reset for next graph replay
    }
    __syncthreads();

    if (s_last) {
        // All 32 partials for this column are visible (atomics + fences).
        const int b = b0 + t;
        float a = bias[0];
        #pragma unroll
        for (int g = 0; g < NFG; g++)
            a += g_partial[g * B_TOT + b];   // coalesced, L2-hot
        y[b] = a;
    }
}

// weights = softplus(theta); single tiny block.
__global__ __launch_bounds__(256) void weights_kernel(
    const float* __restrict__ theta, float* __restrict__ wout)
{
    const int t = threadIdx.x;
    wout[t] = log1pf(__expf(theta[t]));
}

extern "C" void kernel_launch(void* const* d_in, const int* in_sizes, int n_in,
                              void* d_out, int out_size)
{
    const float* x     = (const float*)d_in[0];
    const float* W1    = (const float*)d_in[1];
    const float* b1    = (const float*)d_in[2];
    const float* W2    = (const float*)d_in[3];
    const float* b2    = (const float*)d_in[4];
    const float* W3    = (const float*)d_in[5];
    const float* b3    = (const float*)d_in[6];
    const float* theta = (const float*)d_in[7];
    const float* bias  = (const float*)d_in[8];

    float* out = (float*)d_out;
    float* y    = out;                 // [B]
    float* wout = out + B_TOT;         // [F]
    float* Z    = out + B_TOT + F_TOT; // [B, F]

    weights_kernel<<<1, F_TOT>>>(theta, wout);

    dim3 grid(B_TOT / BB, F_TOT / FT);   // (128, 32)
    mlp_z_kernel<<<grid, 256>>>(x, W1, b1, W2, b2, W3, b3, theta, bias, Z, y);
}

// round 16
// speedup vs baseline: 1.5924x; 1.0792x over previous
#include <cuda_runtime.h>
#include <cstdint>

#define B_TOT 32768
#define F_TOT 256
#define H1 16
#define H2 8

#define BB 256   // batch elements per block
#define FT 8     // features per block (one warp per feature)
#define NP 4     // f32x2 pairs per thread (8 batch elements)
#define NFG (F_TOT / FT)   // 32 feature groups

typedef unsigned long long u64;

// scratch: per-(feature-group, batch) partial dot products  (4 MB)
__device__ float g_partial[NFG * B_TOT];

__device__ __forceinline__ u64 f2pack(float lo, float hi) {
    u64 r; asm("mov.b64 %0, {%1, %2};" : "=l"(r) : "f"(lo), "f"(hi)); return r;
}
__device__ __forceinline__ void f2unpack(u64 p, float& lo, float& hi) {
    asm("mov.b64 {%0, %1}, %2;" : "=f"(lo), "=f"(hi) : "l"(p));
}
__device__ __forceinline__ u64 fma2(u64 a, u64 b, u64 c) {
    u64 r; asm("fma.rn.f32x2 %0, %1, %2, %3;" : "=l"(r) : "l"(a), "l"(b), "l"(c)); return r;
}
__device__ __forceinline__ float ex2f(float x) {
    float r; asm("ex2.approx.ftz.f32 %0, %1;" : "=f"(r) : "f"(x)); return r;
}

// Packed ELU, proven R3/R5/R7 version — do not modify:
// unpack + 2x FMUL-imm + 2x MUFU + 2x FADD + 2x FSETP/FSEL + pack
__device__ __forceinline__ u64 elu2(u64 v2) {
    float v0, v1; f2unpack(v2, v0, v1);
    float e0 = ex2f(v0 * 1.4426950408889634f);
    float e1 = ex2f(v1 * 1.4426950408889634f);
    float r0 = v0 > 0.0f ? v0 : e0 - 1.0f;
    float r1 = v1 > 0.0f ? v1 : e1 - 1.0f;
    return f2pack(r0, r1);
}

__global__ __launch_bounds__(256) void mlp_z_kernel(
    const float* __restrict__ x,
    const float* __restrict__ W1, const float* __restrict__ b1,
    const float* __restrict__ W2, const float* __restrict__ b2,
    const float* __restrict__ W3, const float* __restrict__ b3,
    const float* __restrict__ theta,
    float* __restrict__ Z)
{
    __shared__ float s_x[FT][BB];     // 8 KB
    __shared__ float s_z[FT][BB];     // 8 KB
    // Duplicated {w, w} pairs: packed operand in one broadcast LDS.64
    __shared__ u64 sW1d[FT * H1];
    __shared__ u64 sb1d[FT * H1];
    __shared__ u64 sW2d[FT * H1 * H2];
    __shared__ u64 sb2d[FT * H2];
    __shared__ u64 sW3d[FT * H2];
    __shared__ float sb3[FT];
    __shared__ float s_sw[FT];        // softplus(theta) for this feature group

    const int t  = threadIdx.x;
    const int b0 = blockIdx.x * BB;
    const int f0 = blockIdx.y * FT;

    // ---- params -> smem (duplicated into f32x2) ----
    if (t < FT * H1) {
        float w = W1[f0 * H1 + t];  sW1d[t] = f2pack(w, w);
        float b = b1[f0 * H1 + t];  sb1d[t] = f2pack(b, b);
    }
    #pragma unroll
    for (int i = t; i < FT * H1 * H2; i += 256) {
        float w = W2[f0 * H1 * H2 + i];  sW2d[i] = f2pack(w, w);
    }
    if (t < FT * H2) {
        float b = b2[f0 * H2 + t];  sb2d[t] = f2pack(b, b);
        float w = W3[f0 * H2 + t];  sW3d[t] = f2pack(w, w);
    }
    if (t < FT) {
        sb3[t] = b3[f0 + t];
        s_sw[t] = log1pf(__expf(theta[f0 + t]));
    }

    // ---- x tile [BB x FT] coalesced float4 -> f-major smem ----
    #pragma unroll
    for (int i = t; i < BB * 2; i += 256) {
        const int bl = i >> 1;
        const int fq = (i & 1) * 4;
        const float4 v = *reinterpret_cast<const float4*>(
            x + (size_t)(b0 + bl) * F_TOT + f0 + fq);
        s_x[fq + 0][bl] = v.x;
        s_x[fq + 1][bl] = v.y;
        s_x[fq + 2][bl] = v.z;
        s_x[fq + 3][bl] = v.w;
    }
    __syncthreads();

    const int w = t >> 5;
    const int l = t & 31;

    u64 xp[NP];
    #pragma unroll
    for (int u = 0; u < NP; u++)
        xp[u] = f2pack(s_x[w][l + 64 * u], s_x[w][l + 64 * u + 32]);

    u64 acc[NP][H2];
    #pragma unroll
    for (int k = 0; k < H2; k++) {
        const u64 bv = sb2d[w * H2 + k];
        #pragma unroll
        for (int u = 0; u < NP; u++) acc[u][k] = bv;
    }

    #pragma unroll
    for (int h = 0; h < H1; h++) {
        const u64 w1 = sW1d[w * H1 + h];
        const u64 bb = sb1d[w * H1 + h];
        u64 h1p[NP];
        #pragma unroll
        for (int u = 0; u < NP; u++)
            h1p[u] = elu2(fma2(xp[u], w1, bb));
        #pragma unroll
        for (int k = 0; k < H2; k++) {
            const u64 w2 = sW2d[(w * H1 + h) * H2 + k];
            #pragma unroll
            for (int u = 0; u < NP; u++)
                acc[u][k] = fma2(h1p[u], w2, acc[u][k]);
        }
    }

    // epilogue: Z = elu(acc) . W3 + b3
    {
        const float b3v = sb3[w];
        #pragma unroll
        for (int u = 0; u < NP; u++) {
            u64 z = f2pack(b3v, b3v);
            #pragma unroll
            for (int k = 0; k < H2; k++)
                z = fma2(elu2(acc[u][k]), sW3d[w * H2 + k], z);
            float z0, z1; f2unpack(z, z0, z1);
            s_z[w][l + 64 * u]      = z0;
            s_z[w][l + 64 * u + 32] = z1;
        }
    }
    __syncthreads();

    // ---- Z tile -> gmem coalesced float4 ----
    #pragma unroll
    for (int i = t; i < BB * 2; i += 256) {
        const int bl = i >> 1;
        const int fq = (i & 1) * 4;
        float4 v;
        v.x = s_z[fq + 0][bl];
        v.y = s_z[fq + 1][bl];
        v.z = s_z[fq + 2][bl];
        v.w = s_z[fq + 3][bl];
        *reinterpret_cast<float4*>(Z + (size_t)(b0 + bl) * F_TOT + f0 + fq) = v;
    }

    // ---- fused partial reduction: ps[b] = sum_f s_z[f][b] * softplus(theta[f]) ----
    {
        float ps = 0.0f;
        #pragma unroll
        for (int f = 0; f < FT; f++)
            ps = fmaf(s_z[f][t], s_sw[f], ps);
        g_partial[blockIdx.y * B_TOT + b0 + t] = ps;
    }

    // PDL: allow the dependent reduce kernel to begin scheduling.
    asm volatile("griddepcontrol.launch_dependents;");
}

// Final reduction: 4 threads per batch element, smem combine (proven R7 body)
// + PDL wait: primary grid's stores are guaranteed visible after this.
__global__ __launch_bounds__(256) void reduce2_kernel(
    const float* __restrict__ theta,
    const float* __restrict__ bias,
    float* __restrict__ y,
    float* __restrict__ wout)
{
    __shared__ float s_p[256];
    const int t  = threadIdx.x;
    const int bl = t & 63;        // batch element within block
    const int q  = t >> 6;        // quarter: which 8 feature-groups

    if (blockIdx.x < 4) {
        const int f = blockIdx.x * 64 + bl;
        if (q == 0) wout[f] = log1pf(__expf(theta[f]));
    }

    // Wait for the primary (mlp_z) grid's memory to be visible.
    asm volatile("griddepcontrol.wait;");

    const int b = blockIdx.x * 64 + bl;
    float a = 0.0f;
    #pragma unroll
    for (int g = 0; g < NFG / 4; g++)
        a += g_partial[(q * (NFG / 4) + g) * B_TOT + b];
    s_p[t] = a;
    __syncthreads();

    if (t < 64) {
        float r = bias[0] + s_p[t] + s_p[t + 64] + s_p[t + 128] + s_p[t + 192];
        y[b] = r;
    }
}

extern "C" void kernel_launch(void* const* d_in, const int* in_sizes, int n_in,
                              void* d_out, int out_size)
{
    const float* x     = (const float*)d_in[0];
    const float* W1    = (const float*)d_in[1];
    const float* b1    = (const float*)d_in[2];
    const float* W2    = (const float*)d_in[3];
    const float* b2    = (const float*)d_in[4];
    const float* W3    = (const float*)d_in[5];
    const float* b3    = (const float*)d_in[6];
    const float* theta = (const float*)d_in[7];
    const float* bias  = (const float*)d_in[8];

    float* out = (float*)d_out;
    float* y    = out;                 // [B]
    float* wout = out + B_TOT;         // [F]
    float* Z    = out + B_TOT + F_TOT; // [B, F]

    dim3 grid(B_TOT / BB, F_TOT / FT);   // (128, 32)
    mlp_z_kernel<<<grid, 256>>>(x, W1, b1, W2, b2, W3, b3, theta, Z);

    // Launch reduce2 with Programmatic Dependent Launch so its block ramp
    // overlaps mlp_z's tail wave. griddepcontrol.wait inside the kernel
    // enforces correctness (primary memory flush).
    {
        cudaLaunchConfig_t cfg = {};
        cfg.gridDim  = dim3(B_TOT / 64, 1, 1);   // 512 blocks
        cfg.blockDim = dim3(256, 1, 1);
        cfg.dynamicSmemBytes = 0;
        cfg.stream = 0;
        cudaLaunchAttribute attrs[1];
        attrs[0].id = cudaLaunchAttributeProgrammaticStreamSerialization;
        attrs[0].val.programmaticStreamSerializationAllowed = 1;
        cfg.attrs = attrs;
        cfg.numAttrs = 1;
        cudaLaunchKernelEx(&cfg, reduce2_kernel, theta, bias, y, wout);
    }
}